// round 13
// baseline (speedup 1.0000x reference)
#include <cuda_runtime.h>
#include <cuda_bf16.h>
#include <math.h>

// out[b,n] = MARGIN - <t,t>_M - <h,h>_M + 2 * t . g_b
//            + tanh(bias_head[u_b]) + tanh(bias_tail[v_bn])
// g_b = Q_t B_t G' B_h Q_h^T h_b  (Lorentz invariance: tails never transformed)

#define DIMV 32
#define DV   31
#define MARGIN_C 0.85f

__device__ float g_buf[4096 * DIMV];
__device__ float c_buf[4096];

static __device__ __forceinline__ float wsum(float v) {
#pragma unroll
    for (int o = 16; o > 0; o >>= 1)
        v += __shfl_xor_sync(0xffffffffu, v, o);
    return v;
}

static __device__ __forceinline__ float gelu_exact(float a) {
    return 0.5f * a * (1.0f + erff(a * 0.70710678118654752f));
}

// One warp per block, one sample b per warp (R3 config — measured fastest).
// Lane l holds component l (lane 0 = time component). All weights prefetched
// into registers (MLP~62) and gelu/tanh'd before the serial 62-step chain.
__global__ void __launch_bounds__(32) prep_kernel(
    const int* __restrict__ u_arr, const int* __restrict__ r_arr,
    const float* __restrict__ emb, const float* __restrict__ bias_head,
    const float* __restrict__ hrw, const float* __restrict__ hbw,
    const float* __restrict__ trw, const float* __restrict__ tbw,
    int B)
{
    int b = blockIdx.x;
    if (b >= B) return;
    int lane = threadIdx.x;

    int uu = u_arr[b];
    int rr = r_arr[b];

    // ---- prefetch everything (independent LDGs, huge MLP) ----
    float hwr[DV], twr[DV];
    {
        const float* hb_ = hrw + (size_t)rr * (DV * DV);
        const float* tb_ = trw + (size_t)rr * (DV * DV);
#pragma unroll
        for (int k = 0; k < DV; k++) {
            hwr[k] = (lane >= 1) ? hb_[k * DV + (lane - 1)] : 0.0f;
            twr[k] = (lane >= 1) ? tb_[k * DV + (lane - 1)] : 0.0f;
        }
    }
    float hboost_raw = (lane >= 1) ? hbw[(size_t)rr * DV + (lane - 1)] : 0.0f;
    float tboost_raw = (lane >= 1) ? tbw[(size_t)rr * DV + (lane - 1)] : 0.0f;
    float x  = emb[(size_t)uu * DIMV + lane];
    float bh = bias_head[uu];

    // ---- nonlinearities off the critical chain ----
#pragma unroll
    for (int k = 0; k < DV; k++) hwr[k] = gelu_exact(hwr[k]);
#pragma unroll
    for (int k = 0; k < DV; k++) twr[k] = gelu_exact(twr[k]);
    float hro = tanhf(hboost_raw) * (1.0f / 32.0f);
    float tro = tanhf(tboost_raw) * (1.0f / 32.0f);

    // ---- norms: 62 independent reductions, pipelined (ILP), then fast div ----
    float hinv[DV], tinv[DV];
#pragma unroll
    for (int k = 0; k < DV; k++) { hinv[k] = hwr[k] * hwr[k]; tinv[k] = twr[k] * twr[k]; }
#pragma unroll
    for (int o = 16; o > 0; o >>= 1) {
#pragma unroll
        for (int k = 0; k < DV; k++) {
            hinv[k] += __shfl_xor_sync(0xffffffffu, hinv[k], o);
            tinv[k] += __shfl_xor_sync(0xffffffffu, tinv[k], o);
        }
    }
#pragma unroll
    for (int k = 0; k < DV; k++) {
        hinv[k] = __fdividef(2.0f, hinv[k]);
        tinv[k] = __fdividef(2.0f, tinv[k]);
    }

    // ---- boost coefficients (independent of x) ----
    float hv2 = wsum(hro * hro);
    float tv2 = wsum(tro * tro);
    float hzeta = __fdividef(1.0f, sqrtf(1.0f - hv2) + 1e-8f);
    float tzeta = __fdividef(1.0f, sqrtf(1.0f - tv2) + 1e-8f);
    float hc2 = __fdividef(hzeta - 1.0f, hv2 + 1e-9f);
    float tc2 = __fdividef(tzeta - 1.0f, tv2 + 1e-9f);

    // ---- <h,h>_M ----
    float h0 = __shfl_sync(0xffffffffu, x, 0);
    float hh = wsum(x * x) - 2.0f * h0 * h0;

    // ---- head rotation: apply H_0 .. H_30 (= Q_h^T x) ----
#pragma unroll
    for (int k = 0; k < DV; k++) {
        float d = wsum(hwr[k] * x);
        x -= (d * hinv[k]) * hwr[k];
    }
    // ---- head boost ----
    {
        float dot = wsum(hro * x);
        float x0  = __shfl_sync(0xffffffffu, x, 0);
        x = (lane == 0) ? (hzeta * x0 - hzeta * dot)
                        : (-hzeta * x0 * hro + x + hc2 * hro * dot);
    }
    // ---- G' ----
    if (lane == 0) x = -x;
    // ---- tail boost (symmetric) ----
    {
        float dot = wsum(tro * x);
        float x0  = __shfl_sync(0xffffffffu, x, 0);
        x = (lane == 0) ? (tzeta * x0 - tzeta * dot)
                        : (-tzeta * x0 * tro + x + tc2 * tro * dot);
    }
    // ---- tail rotation: apply H_30 .. H_0 (= Q_t x) ----
#pragma unroll
    for (int k = DV - 1; k >= 0; k--) {
        float d = wsum(twr[k] * x);
        x -= (d * tinv[k]) * twr[k];
    }

    g_buf[(size_t)b * DIMV + lane] = 2.0f * x;
    if (lane == 0)
        c_buf[b] = MARGIN_C - hh + tanhf(bh);
}

// Forced-in-flight gather with L2 evict_last retention (createpolicy +
// cache_hint). asm volatile pins all 8 loads in flight before any consumer.
static __device__ __forceinline__ float4 ldg_evict_last_v4(const float4* p,
                                                           unsigned long long pol) {
    float4 v;
    asm volatile("ld.global.nc.L2::cache_hint.v4.f32 {%0,%1,%2,%3}, [%4], %5;"
                 : "=f"(v.x), "=f"(v.y), "=f"(v.z), "=f"(v.w)
                 : "l"(p), "l"(pol));
    return v;
}

// R6 score body with one change: the block's 256 tail indices are staged into
// SMEM by a single coalesced load at kernel start, so every gather's address
// comes from a 29-cyc LDS instead of a ~600-cyc scattered LDG (removes one
// DRAM-latency level from the dependency chain). The 8 gathers per thread stay
// fully independent and pinned in flight; post-transpose 128B coalesced store.
__global__ void __launch_bounds__(256) score_kernel(
    const int* __restrict__ v_arr, const float* __restrict__ emb,
    const float* __restrict__ bias_tail,
    float* __restrict__ out, int N)
{
    int b = blockIdx.x;
    __shared__ float4 g4s[8];
    __shared__ float  cbs;
    __shared__ int    sidx[256];

    unsigned long long pol;
    asm("createpolicy.fractional.L2::evict_last.b64 %0, 1.0;" : "=l"(pol));

    int tid = threadIdx.x;
    const int* vrow = v_arr + (size_t)b * N;

    // one coalesced index load for the whole block
    if (tid < N) sidx[tid] = vrow[tid];
    if (tid < 8) g4s[tid] = ((const float4*)(g_buf + (size_t)b * DIMV))[tid];
    if (tid == 0) cbs = c_buf[b];
    __syncthreads();

    int lane = tid & 31;
    int warp = tid >> 5;
    int q    = lane & 7;
    int grp  = lane >> 3;
    float4 gq = g4s[q];
    float  cb = cbs;

    const float4* emb4 = (const float4*)emb;
    float* orow = out + (size_t)b * N;

    for (int base = warp * 32; base < N; base += 256) {
        int idxs[8];
#pragma unroll
        for (int it = 0; it < 8; ++it) {
            int n = base + it * 4 + grp;
            idxs[it] = (n < N) ? sidx[n & 255] : 0;
        }
        // all 8 gathers pinned in flight (asm volatile, issue order preserved)
        float4 tvs[8];
#pragma unroll
        for (int it = 0; it < 8; ++it)
            tvs[it] = ldg_evict_last_v4(emb4 + (size_t)idxs[it] * 8 + q, pol);
        float bts[8];
#pragma unroll
        for (int it = 0; it < 8; ++it)
            bts[it] = (q == 0) ? bias_tail[idxs[it]] : 0.0f;

        float vals[8];
#pragma unroll
        for (int it = 0; it < 8; ++it) {
            float4 tv = tvs[it];
            float val = tv.x * (gq.x - tv.x) + tv.y * (gq.y - tv.y)
                      + tv.z * (gq.z - tv.z) + tv.w * (gq.w - tv.w);
            if (q == 0) val += 2.0f * tv.x * tv.x;
            val += __shfl_xor_sync(0xffffffffu, val, 1);
            val += __shfl_xor_sync(0xffffffffu, val, 2);
            val += __shfl_xor_sync(0xffffffffu, val, 4);
            vals[it] = val + cb + tanhf(bts[it]);   // complete at q==0 lanes
        }

        // transpose: lane L takes row base+L from iteration L>>2, lane (L&3)*8
        float outv = 0.0f;
#pragma unroll
        for (int it = 0; it < 8; ++it) {
            float t = __shfl_sync(0xffffffffu, vals[it], (lane & 3) << 3);
            if ((lane >> 2) == it) outv = t;
        }
        int n = base + lane;
        if (n < N) orow[n] = outv;   // 128B coalesced per warp
    }
}

extern "C" void kernel_launch(void* const* d_in, const int* in_sizes, int n_in,
                              void* d_out, int out_size) {
    const int*   u         = (const int*)  d_in[0];
    const int*   r         = (const int*)  d_in[1];
    const int*   v         = (const int*)  d_in[2];
    const float* emb       = (const float*)d_in[3];
    const float* bias_head = (const float*)d_in[4];
    const float* bias_tail = (const float*)d_in[5];
    const float* hrw       = (const float*)d_in[6];
    const float* hbw       = (const float*)d_in[7];
    const float* trw       = (const float*)d_in[8];
    const float* tbw       = (const float*)d_in[9];
    float* out = (float*)d_out;

    int B = in_sizes[0];
    int N = in_sizes[2] / B;

    prep_kernel<<<B, 32>>>(u, r, emb, bias_head, hrw, hbw, trw, tbw, B);
    score_kernel<<<B, 256>>>(v, emb, bias_tail, out, N);
}

// round 16
// speedup vs baseline: 1.1023x; 1.1023x over previous
#include <cuda_runtime.h>
#include <cuda_bf16.h>
#include <math.h>

// out[b,n] = MARGIN - <t,t>_M - <h,h>_M + 2 * t . g_b
//            + tanh(bias_head[u_b]) + tanh(bias_tail[v_bn])
// g_b = Q_t B_t G' B_h Q_h^T h_b  (Lorentz invariance: tails never transformed)

#define DIMV 32
#define DV   31
#define MARGIN_C 0.85f

__device__ float g_buf[4096 * DIMV];
__device__ float c_buf[4096];

static __device__ __forceinline__ float wsum(float v) {
#pragma unroll
    for (int o = 16; o > 0; o >>= 1)
        v += __shfl_xor_sync(0xffffffffu, v, o);
    return v;
}

static __device__ __forceinline__ float gelu_exact(float a) {
    return 0.5f * a * (1.0f + erff(a * 0.70710678118654752f));
}

// One warp per sample b (R6-measured prep: pair-compacted Householder chain).
// Weights prefetched (MLP~62), gelu'd, normalized to w~ = sqrt(2)/||w|| * w so
// H = I - w~ w~^T. Reflections applied in PAIRS via the compact recurrence
//   e0 = w~a.x ; d1 = w~b.x - (w~b.w~a) e0 ; x -= e0 w~a + d1 w~b
// halving the serial reduction depth. Pair cross-terms precomputed in the
// prologue as pipelined parallel reductions.
__global__ void __launch_bounds__(32) prep_kernel(
    const int* __restrict__ u_arr, const int* __restrict__ r_arr,
    const float* __restrict__ emb, const float* __restrict__ bias_head,
    const float* __restrict__ hrw, const float* __restrict__ hbw,
    const float* __restrict__ trw, const float* __restrict__ tbw,
    int B)
{
    int b = blockIdx.x;
    if (b >= B) return;
    int lane = threadIdx.x;

    int uu = u_arr[b];
    int rr = r_arr[b];

    // ---- prefetch everything (independent LDGs, huge MLP) ----
    float hwr[DV], twr[DV];
    {
        const float* hb_ = hrw + (size_t)rr * (DV * DV);
        const float* tb_ = trw + (size_t)rr * (DV * DV);
#pragma unroll
        for (int k = 0; k < DV; k++) {
            hwr[k] = (lane >= 1) ? hb_[k * DV + (lane - 1)] : 0.0f;
            twr[k] = (lane >= 1) ? tb_[k * DV + (lane - 1)] : 0.0f;
        }
    }
    float hboost_raw = (lane >= 1) ? hbw[(size_t)rr * DV + (lane - 1)] : 0.0f;
    float tboost_raw = (lane >= 1) ? tbw[(size_t)rr * DV + (lane - 1)] : 0.0f;
    float x  = emb[(size_t)uu * DIMV + lane];
    float bh = bias_head[uu];

    // ---- nonlinearities (off the serial chain) ----
#pragma unroll
    for (int k = 0; k < DV; k++) hwr[k] = gelu_exact(hwr[k]);
#pragma unroll
    for (int k = 0; k < DV; k++) twr[k] = gelu_exact(twr[k]);
    float hro = tanhf(hboost_raw) * (1.0f / 32.0f);
    float tro = tanhf(tboost_raw) * (1.0f / 32.0f);

    // ---- norms (62 pipelined reductions) then scale: w~ = sqrt(2/n2) w ----
    {
        float hn[DV], tn[DV];
#pragma unroll
        for (int k = 0; k < DV; k++) { hn[k] = hwr[k] * hwr[k]; tn[k] = twr[k] * twr[k]; }
#pragma unroll
        for (int o = 16; o > 0; o >>= 1) {
#pragma unroll
            for (int k = 0; k < DV; k++) {
                hn[k] += __shfl_xor_sync(0xffffffffu, hn[k], o);
                tn[k] += __shfl_xor_sync(0xffffffffu, tn[k], o);
            }
        }
#pragma unroll
        for (int k = 0; k < DV; k++) {
            hwr[k] *= sqrtf(2.0f) * rsqrtf(hn[k]);
            twr[k] *= sqrtf(2.0f) * rsqrtf(tn[k]);
        }
    }

    // ---- pair cross-terms (pipelined reductions, x-independent) ----
    float ch[15], ct[15];
#pragma unroll
    for (int p = 0; p < 15; p++) {
        ch[p] = hwr[2 * p] * hwr[2 * p + 1];
        ct[p] = twr[30 - 2 * p] * twr[29 - 2 * p];
    }
#pragma unroll
    for (int o = 16; o > 0; o >>= 1) {
#pragma unroll
        for (int p = 0; p < 15; p++) {
            ch[p] += __shfl_xor_sync(0xffffffffu, ch[p], o);
            ct[p] += __shfl_xor_sync(0xffffffffu, ct[p], o);
        }
    }

    // ---- boost coefficients (independent of x) ----
    float hv2 = wsum(hro * hro);
    float tv2 = wsum(tro * tro);
    float hzeta = __fdividef(1.0f, sqrtf(1.0f - hv2) + 1e-8f);
    float tzeta = __fdividef(1.0f, sqrtf(1.0f - tv2) + 1e-8f);
    float hc2 = __fdividef(hzeta - 1.0f, hv2 + 1e-9f);
    float tc2 = __fdividef(tzeta - 1.0f, tv2 + 1e-9f);

    // ---- <h,h>_M ----
    float h0 = __shfl_sync(0xffffffffu, x, 0);
    float hh = wsum(x * x) - 2.0f * h0 * h0;

    // ---- head rotation: H_0 .. H_30 in pairs ----
#pragma unroll
    for (int p = 0; p < 15; p++) {
        float e0 = hwr[2 * p] * x;
        float e1 = hwr[2 * p + 1] * x;
#pragma unroll
        for (int o = 16; o > 0; o >>= 1) {
            e0 += __shfl_xor_sync(0xffffffffu, e0, o);
            e1 += __shfl_xor_sync(0xffffffffu, e1, o);
        }
        float d1 = e1 - ch[p] * e0;
        x -= e0 * hwr[2 * p] + d1 * hwr[2 * p + 1];
    }
    { float d = wsum(hwr[30] * x); x -= d * hwr[30]; }

    // ---- head boost ----
    {
        float dot = wsum(hro * x);
        float x0  = __shfl_sync(0xffffffffu, x, 0);
        x = (lane == 0) ? (hzeta * x0 - hzeta * dot)
                        : (-hzeta * x0 * hro + x + hc2 * hro * dot);
    }
    // ---- G' ----
    if (lane == 0) x = -x;
    // ---- tail boost (symmetric) ----
    {
        float dot = wsum(tro * x);
        float x0  = __shfl_sync(0xffffffffu, x, 0);
        x = (lane == 0) ? (tzeta * x0 - tzeta * dot)
                        : (-tzeta * x0 * tro + x + tc2 * tro * dot);
    }
    // ---- tail rotation: H_30 .. H_0 in pairs ----
#pragma unroll
    for (int p = 0; p < 15; p++) {
        float e0 = twr[30 - 2 * p] * x;
        float e1 = twr[29 - 2 * p] * x;
#pragma unroll
        for (int o = 16; o > 0; o >>= 1) {
            e0 += __shfl_xor_sync(0xffffffffu, e0, o);
            e1 += __shfl_xor_sync(0xffffffffu, e1, o);
        }
        float d1 = e1 - ct[p] * e0;
        x -= e0 * twr[30 - 2 * p] + d1 * twr[29 - 2 * p];
    }
    { float d = wsum(twr[0] * x); x -= d * twr[0]; }

    g_buf[(size_t)b * DIMV + lane] = 2.0f * x;
    if (lane == 0)
        c_buf[b] = MARGIN_C - hh + tanhf(bh);
}

// Forced-in-flight gather with L2 evict_last retention (createpolicy +
// cache_hint). asm volatile pins all 8 loads in flight before any consumer.
static __device__ __forceinline__ float4 ldg_evict_last_v4(const float4* p,
                                                           unsigned long long pol) {
    float4 v;
    asm volatile("ld.global.nc.L2::cache_hint.v4.f32 {%0,%1,%2,%3}, [%4], %5;"
                 : "=f"(v.x), "=f"(v.y), "=f"(v.z), "=f"(v.w)
                 : "l"(p), "l"(pol));
    return v;
}

// R6 score body with ONE change: bias_tail is handled per-output-row AFTER the
// transpose (1 coalesced idx load + 1 scattered 4B load + 1 tanhf per thread,
// issued at iteration start in parallel with the gathers) instead of 8 tanhf +
// 8 scattered loads per thread. Gather structure untouched.
__global__ void __launch_bounds__(256) score_kernel(
    const int* __restrict__ v_arr, const float* __restrict__ emb,
    const float* __restrict__ bias_tail,
    float* __restrict__ out, int N)
{
    int b = blockIdx.x;
    __shared__ float4 g4s[8];
    __shared__ float  cbs;

    unsigned long long pol;
    asm("createpolicy.fractional.L2::evict_last.b64 %0, 1.0;" : "=l"(pol));

    int tid = threadIdx.x;
    if (tid < 8) g4s[tid] = ((const float4*)(g_buf + (size_t)b * DIMV))[tid];
    if (tid == 0) cbs = c_buf[b];
    __syncthreads();

    int lane = tid & 31;
    int warp = tid >> 5;
    int q    = lane & 7;
    int grp  = lane >> 3;
    float4 gq = g4s[q];
    float  cb = cbs;

    const float4* emb4 = (const float4*)emb;
    const int* vrow = v_arr + (size_t)b * N;
    float* orow = out + (size_t)b * N;

    for (int base = warp * 32; base < N; base += 256) {
        int nme = base + lane;
        // own-row index (coalesced) + bias load: issued early, consumed last
        int myidx = (nme < N) ? vrow[nme] : 0;
        float btv = bias_tail[myidx];

        int idxs[8];
#pragma unroll
        for (int it = 0; it < 8; ++it) {
            int n = base + it * 4 + grp;
            idxs[it] = (n < N) ? vrow[n] : 0;
        }
        // all 8 gathers pinned in flight (asm volatile, issue order preserved)
        float4 tvs[8];
#pragma unroll
        for (int it = 0; it < 8; ++it)
            tvs[it] = ldg_evict_last_v4(emb4 + (size_t)idxs[it] * 8 + q, pol);

        float vals[8];
#pragma unroll
        for (int it = 0; it < 8; ++it) {
            float4 tv = tvs[it];
            float val = tv.x * (gq.x - tv.x) + tv.y * (gq.y - tv.y)
                      + tv.z * (gq.z - tv.z) + tv.w * (gq.w - tv.w);
            if (q == 0) val += 2.0f * tv.x * tv.x;
            val += __shfl_xor_sync(0xffffffffu, val, 1);
            val += __shfl_xor_sync(0xffffffffu, val, 2);
            val += __shfl_xor_sync(0xffffffffu, val, 4);
            vals[it] = val + cb;                 // complete at q==0 lanes
        }

        // transpose: lane L takes row base+L from iteration L>>2, lane (L&3)*8
        float outv = 0.0f;
#pragma unroll
        for (int it = 0; it < 8; ++it) {
            float t = __shfl_sync(0xffffffffu, vals[it], (lane & 3) << 3);
            if ((lane >> 2) == it) outv = t;
        }
        if (nme < N)
            orow[nme] = outv + tanhf(btv);       // 128B coalesced per warp
    }
}

extern "C" void kernel_launch(void* const* d_in, const int* in_sizes, int n_in,
                              void* d_out, int out_size) {
    const int*   u         = (const int*)  d_in[0];
    const int*   r         = (const int*)  d_in[1];
    const int*   v         = (const int*)  d_in[2];
    const float* emb       = (const float*)d_in[3];
    const float* bias_head = (const float*)d_in[4];
    const float* bias_tail = (const float*)d_in[5];
    const float* hrw       = (const float*)d_in[6];
    const float* hbw       = (const float*)d_in[7];
    const float* trw       = (const float*)d_in[8];
    const float* tbw       = (const float*)d_in[9];
    float* out = (float*)d_out;

    int B = in_sizes[0];
    int N = in_sizes[2] / B;

    prep_kernel<<<B, 32>>>(u, r, emb, bias_head, hrw, hbw, trw, tbw, B);
    score_kernel<<<B, 256>>>(v, emb, bias_tail, out, N);
}